// round 2
// baseline (speedup 1.0000x reference)
#include <cuda_runtime.h>
#include <cuda_bf16.h>
#include <cstdint>

#define N_NODES   100000
#define N_EDGES   1600000
#define IN_FEATS  128
#define OUT_FEATS 64

// Scratch: projected features h = feat @ W^T + b, stored as float4 chunks.
// 100000 * 64 floats = 25.6 MB (fits L2).
__device__ float4 g_h4[N_NODES * (OUT_FEATS / 4)];

// ---------------------------------------------------------------------------
// Kernel 1: dense projection  h[n][o] = sum_k feat[n][k] * W[o][k] + b[o]
// block = 256 threads, NODES_PER_BLOCK = 16.
// Thread (ng, o): ng = tid/64 in [0,4), o = tid%64; handles nodes ng, ng+4, ng+8, ng+12.
// W transposed into smem: Wt[k*64 + o] -> conflict-free reads (consecutive o per warp).
// ---------------------------------------------------------------------------
#define NODES_PER_BLOCK 16

__global__ __launch_bounds__(256) void proj_kernel(
    const float* __restrict__ feat,
    const float* __restrict__ W_w,   // [64][128]
    const float* __restrict__ W_b)   // [64]
{
    __shared__ float Wt[IN_FEATS * OUT_FEATS];          // 32 KB, Wt[k*64+o]
    __shared__ float featS[NODES_PER_BLOCK * IN_FEATS]; // 8 KB

    const int tid = threadIdx.x;
    const int nodeBase = blockIdx.x * NODES_PER_BLOCK;

    // Load W transposed
    #pragma unroll 4
    for (int idx = tid; idx < OUT_FEATS * IN_FEATS; idx += 256) {
        int o = idx >> 7;          // /128
        int k = idx & 127;
        Wt[k * OUT_FEATS + o] = W_w[idx];
    }
    // Load feat tile
    #pragma unroll 4
    for (int idx = tid; idx < NODES_PER_BLOCK * IN_FEATS; idx += 256) {
        int n = nodeBase + (idx >> 7);
        featS[idx] = (n < N_NODES) ? feat[(size_t)n * IN_FEATS + (idx & 127)] : 0.0f;
    }
    __syncthreads();

    const int o  = tid & 63;
    const int ng = tid >> 6;   // 0..3

    float acc0 = 0.f, acc1 = 0.f, acc2 = 0.f, acc3 = 0.f;
    #pragma unroll 8
    for (int k = 0; k < IN_FEATS; k++) {
        float w = Wt[k * OUT_FEATS + o];
        acc0 += featS[(ng +  0) * IN_FEATS + k] * w;
        acc1 += featS[(ng +  4) * IN_FEATS + k] * w;
        acc2 += featS[(ng +  8) * IN_FEATS + k] * w;
        acc3 += featS[(ng + 12) * IN_FEATS + k] * w;
    }
    float b = W_b[o];
    float* hout = (float*)g_h4;
    int n0 = nodeBase + ng;
    if (n0 +  0 < N_NODES) hout[(size_t)(n0 +  0) * OUT_FEATS + o] = acc0 + b;
    if (n0 +  4 < N_NODES) hout[(size_t)(n0 +  4) * OUT_FEATS + o] = acc1 + b;
    if (n0 +  8 < N_NODES) hout[(size_t)(n0 +  8) * OUT_FEATS + o] = acc2 + b;
    if (n0 + 12 < N_NODES) hout[(size_t)(n0 + 12) * OUT_FEATS + o] = acc3 + b;
}

// ---------------------------------------------------------------------------
// Kernel 2: edge gather + scale + scatter-add.
// 16 threads per edge; thread c handles float4 chunk c of the 64-float row.
// red.global.add.v4.f32 : vectorized atomic, 4x fewer atomic ops.
// NOTE: src/dst are int32 (JAX default x64-disabled downcasts jnp.int64).
// ---------------------------------------------------------------------------
__device__ __forceinline__ void red_add_v4(float* p, float x, float y, float z, float w) {
    asm volatile("red.global.add.v4.f32 [%0], {%1, %2, %3, %4};"
                 :: "l"(p), "f"(x), "f"(y), "f"(z), "f"(w) : "memory");
}

__global__ __launch_bounds__(256) void edge_kernel(
    const int* __restrict__ src,
    const int* __restrict__ dst,
    const float* __restrict__ e,
    float* __restrict__ out)
{
    unsigned int t = blockIdx.x * 256u + threadIdx.x;   // < N_EDGES*16
    unsigned int edge = t >> 4;
    unsigned int c    = t & 15;
    if (edge >= N_EDGES) return;

    int s = __ldg(src + edge);
    int d = __ldg(dst + edge);
    float w = __ldg(e + edge);

    float4 h = g_h4[(size_t)s * 16 + c];
    float* p = out + ((size_t)d * OUT_FEATS + c * 4);
    red_add_v4(p, h.x * w, h.y * w, h.z * w, h.w * w);
}

// ---------------------------------------------------------------------------
// Kernel 3: in-place ReLU on output.
// ---------------------------------------------------------------------------
__global__ __launch_bounds__(256) void relu_kernel(float4* __restrict__ out, int n4)
{
    int i = blockIdx.x * 256 + threadIdx.x;
    if (i >= n4) return;
    float4 v = out[i];
    v.x = fmaxf(v.x, 0.f);
    v.y = fmaxf(v.y, 0.f);
    v.z = fmaxf(v.z, 0.f);
    v.w = fmaxf(v.w, 0.f);
    out[i] = v;
}

extern "C" void kernel_launch(void* const* d_in, const int* in_sizes, int n_in,
                              void* d_out, int out_size)
{
    const float* feat = (const float*)d_in[0];
    const int*   src  = (const int*)d_in[1];
    const int*   dst  = (const int*)d_in[2];
    const float* e    = (const float*)d_in[3];
    const float* W_w  = (const float*)d_in[4];
    const float* W_b  = (const float*)d_in[5];
    float* out = (float*)d_out;

    // 1. zero accumulator (d_out is poisoned before timing)
    cudaMemsetAsync(out, 0, (size_t)out_size * sizeof(float));

    // 2. projection
    int projBlocks = (N_NODES + NODES_PER_BLOCK - 1) / NODES_PER_BLOCK;
    proj_kernel<<<projBlocks, 256>>>(feat, W_w, W_b);

    // 3. edge scatter
    unsigned int workItems = (unsigned int)N_EDGES * 16u;
    unsigned int edgeBlocks = (workItems + 255u) / 256u;
    edge_kernel<<<edgeBlocks, 256>>>(src, dst, e, out);

    // 4. relu
    int n4 = out_size / 4;
    relu_kernel<<<(n4 + 255) / 256, 256>>>((float4*)out, n4);
}

// round 4
// speedup vs baseline: 2.1353x; 2.1353x over previous
#include <cuda_runtime.h>
#include <cuda_bf16.h>
#include <cstdint>

#define N_NODES   100000
#define N_EDGES   1600000
#define IN_FEATS  128
#define OUT_FEATS 64

// Scratch: projected features h = feat @ W^T + b. 25.6 MB (L2-resident).
__device__ float g_h[N_NODES * OUT_FEATS];

// ---------------------------------------------------------------------------
// Kernel 1: register-tiled projection.
// Block: 256 threads (tx=tid%16, ty=tid/16). TILE_M=64 nodes, N=64 outs.
// Thread computes 4x4 outputs: m = ty + i*16, o = tx + j*16.
// K processed in 2 chunks of 64; feat & W staged row-major in smem, stride 68.
// Per 4-k step: 8 LDS.128 -> 64 FMA (conflict-free banks).
// ---------------------------------------------------------------------------
#define TM      64
#define KCHUNK  64
#define SP      68   // smem row stride in floats (pad 4, keeps 16B alignment)

__global__ __launch_bounds__(256) void proj_kernel(
    const float* __restrict__ feat,
    const float* __restrict__ W_w,   // [64][128]
    const float* __restrict__ W_b)   // [64]
{
    __shared__ float fS[TM * SP];        // 17408 B
    __shared__ float wS[OUT_FEATS * SP]; // 17408 B

    const int tid = threadIdx.x;
    const int tx  = tid & 15;
    const int ty  = tid >> 4;
    const int nodeBase = blockIdx.x * TM;

    float acc[4][4];
    #pragma unroll
    for (int i = 0; i < 4; i++)
        #pragma unroll
        for (int j = 0; j < 4; j++)
            acc[i][j] = 0.0f;

    for (int c = 0; c < 2; c++) {
        // ---- stage chunk c: rows m (feat) and o (W), 16 float4 per row ----
        #pragma unroll
        for (int it = 0; it < 4; it++) {
            int lin = tid + it * 256;      // 0..1023
            int r   = lin >> 4;            // row 0..63
            int k4  = lin & 15;            // float4 index within chunk
            int gcol = c * KCHUNK + k4 * 4;

            int n = nodeBase + r;
            float4 fv = make_float4(0.f, 0.f, 0.f, 0.f);
            if (n < N_NODES)
                fv = *(const float4*)&feat[(size_t)n * IN_FEATS + gcol];
            *(float4*)&fS[r * SP + k4 * 4] = fv;

            float4 wv = *(const float4*)&W_w[(size_t)r * IN_FEATS + gcol];
            *(float4*)&wS[r * SP + k4 * 4] = wv;
        }
        __syncthreads();

        // ---- compute ----
        #pragma unroll 4
        for (int k = 0; k < KCHUNK; k += 4) {
            float4 a[4], b[4];
            #pragma unroll
            for (int i = 0; i < 4; i++)
                a[i] = *(const float4*)&fS[(ty + i * 16) * SP + k];
            #pragma unroll
            for (int j = 0; j < 4; j++)
                b[j] = *(const float4*)&wS[(tx + j * 16) * SP + k];
            #pragma unroll
            for (int i = 0; i < 4; i++)
                #pragma unroll
                for (int j = 0; j < 4; j++) {
                    acc[i][j] += a[i].x * b[j].x;
                    acc[i][j] += a[i].y * b[j].y;
                    acc[i][j] += a[i].z * b[j].z;
                    acc[i][j] += a[i].w * b[j].w;
                }
        }
        __syncthreads();
    }

    // ---- epilogue: add bias, store ----
    float bias[4];
    #pragma unroll
    for (int j = 0; j < 4; j++)
        bias[j] = __ldg(&W_b[tx + j * 16]);

    #pragma unroll
    for (int i = 0; i < 4; i++) {
        int n = nodeBase + ty + i * 16;
        if (n < N_NODES) {
            #pragma unroll
            for (int j = 0; j < 4; j++)
                g_h[(size_t)n * OUT_FEATS + tx + j * 16] = acc[i][j] + bias[j];
        }
    }
}

// ---------------------------------------------------------------------------
// Kernel 2: edge gather + scale + scatter-add (16 threads/edge, v4 atomics).
// ---------------------------------------------------------------------------
__device__ __forceinline__ void red_add_v4(float* p, float x, float y, float z, float w) {
    asm volatile("red.global.add.v4.f32 [%0], {%1, %2, %3, %4};"
                 :: "l"(p), "f"(x), "f"(y), "f"(z), "f"(w) : "memory");
}

__global__ __launch_bounds__(256) void edge_kernel(
    const int* __restrict__ src,
    const int* __restrict__ dst,
    const float* __restrict__ e,
    float* __restrict__ out)
{
    unsigned int t = blockIdx.x * 256u + threadIdx.x;
    unsigned int edge = t >> 4;
    unsigned int c    = t & 15;
    if (edge >= N_EDGES) return;

    int s = __ldg(src + edge);
    int d = __ldg(dst + edge);
    float w = __ldg(e + edge);

    float4 h = *(const float4*)&g_h[(size_t)s * OUT_FEATS + c * 4];
    float* p = out + ((size_t)d * OUT_FEATS + c * 4);
    red_add_v4(p, h.x * w, h.y * w, h.z * w, h.w * w);
}

// ---------------------------------------------------------------------------
// Kernel 3: in-place ReLU.
// ---------------------------------------------------------------------------
__global__ __launch_bounds__(256) void relu_kernel(float4* __restrict__ out, int n4)
{
    int i = blockIdx.x * 256 + threadIdx.x;
    if (i >= n4) return;
    float4 v = out[i];
    v.x = fmaxf(v.x, 0.f);
    v.y = fmaxf(v.y, 0.f);
    v.z = fmaxf(v.z, 0.f);
    v.w = fmaxf(v.w, 0.f);
    out[i] = v;
}

extern "C" void kernel_launch(void* const* d_in, const int* in_sizes, int n_in,
                              void* d_out, int out_size)
{
    const float* feat = (const float*)d_in[0];
    const int*   src  = (const int*)d_in[1];
    const int*   dst  = (const int*)d_in[2];
    const float* e    = (const float*)d_in[3];
    const float* W_w  = (const float*)d_in[4];
    const float* W_b  = (const float*)d_in[5];
    float* out = (float*)d_out;

    cudaMemsetAsync(out, 0, (size_t)out_size * sizeof(float));

    int projBlocks = (N_NODES + TM - 1) / TM;
    proj_kernel<<<projBlocks, 256>>>(feat, W_w, W_b);

    unsigned int workItems = (unsigned int)N_EDGES * 16u;
    edge_kernel<<<(workItems + 255u) / 256u, 256>>>(src, dst, e, out);

    int n4 = out_size / 4;
    relu_kernel<<<(n4 + 255) / 256, 256>>>((float4*)out, n4);
}

// round 5
// speedup vs baseline: 2.7846x; 1.3041x over previous
#include <cuda_runtime.h>
#include <cuda_bf16.h>
#include <cstdint>

#define N_NODES   100000
#define N_EDGES   1600000
#define IN_FEATS  128
#define OUT_FEATS 64

#define SCAN_BLOCKS 98   // ceil(100000/1024)

// ---- scratch (__device__ globals; no allocs allowed) ----
__device__ float g_h[N_NODES * OUT_FEATS];      // projected features (25.6 MB)
__device__ int   g_counts[N_NODES];
__device__ int   g_offsets[N_NODES];
__device__ int   g_cursor[N_NODES];
__device__ int   g_blockSums[SCAN_BLOCKS];
__device__ int   g_blockSumsScanned[SCAN_BLOCKS];
__device__ int2  g_sorted[N_EDGES];             // (src, __float_as_int(e)) sorted by dst

// ---------------------------------------------------------------------------
// Kernel 1: register-tiled projection (unchanged from R4: 55.8us).
// ---------------------------------------------------------------------------
#define TM      64
#define KCHUNK  64
#define SP      68

__global__ __launch_bounds__(256) void proj_kernel(
    const float* __restrict__ feat,
    const float* __restrict__ W_w,
    const float* __restrict__ W_b)
{
    __shared__ float fS[TM * SP];
    __shared__ float wS[OUT_FEATS * SP];

    const int tid = threadIdx.x;
    const int tx  = tid & 15;
    const int ty  = tid >> 4;
    const int nodeBase = blockIdx.x * TM;

    float acc[4][4];
    #pragma unroll
    for (int i = 0; i < 4; i++)
        #pragma unroll
        for (int j = 0; j < 4; j++)
            acc[i][j] = 0.0f;

    for (int c = 0; c < 2; c++) {
        #pragma unroll
        for (int it = 0; it < 4; it++) {
            int lin = tid + it * 256;
            int r   = lin >> 4;
            int k4  = lin & 15;
            int gcol = c * KCHUNK + k4 * 4;

            int n = nodeBase + r;
            float4 fv = make_float4(0.f, 0.f, 0.f, 0.f);
            if (n < N_NODES)
                fv = *(const float4*)&feat[(size_t)n * IN_FEATS + gcol];
            *(float4*)&fS[r * SP + k4 * 4] = fv;

            float4 wv = *(const float4*)&W_w[(size_t)r * IN_FEATS + gcol];
            *(float4*)&wS[r * SP + k4 * 4] = wv;
        }
        __syncthreads();

        #pragma unroll 4
        for (int k = 0; k < KCHUNK; k += 4) {
            float4 a[4], b[4];
            #pragma unroll
            for (int i = 0; i < 4; i++)
                a[i] = *(const float4*)&fS[(ty + i * 16) * SP + k];
            #pragma unroll
            for (int j = 0; j < 4; j++)
                b[j] = *(const float4*)&wS[(tx + j * 16) * SP + k];
            #pragma unroll
            for (int i = 0; i < 4; i++)
                #pragma unroll
                for (int j = 0; j < 4; j++) {
                    acc[i][j] += a[i].x * b[j].x;
                    acc[i][j] += a[i].y * b[j].y;
                    acc[i][j] += a[i].z * b[j].z;
                    acc[i][j] += a[i].w * b[j].w;
                }
        }
        __syncthreads();
    }

    float bias[4];
    #pragma unroll
    for (int j = 0; j < 4; j++)
        bias[j] = __ldg(&W_b[tx + j * 16]);

    #pragma unroll
    for (int i = 0; i < 4; i++) {
        int n = nodeBase + ty + i * 16;
        if (n < N_NODES) {
            #pragma unroll
            for (int j = 0; j < 4; j++)
                g_h[(size_t)n * OUT_FEATS + tx + j * 16] = acc[i][j] + bias[j];
        }
    }
}

// ---------------------------------------------------------------------------
// Counting sort of edges by dst (CSR build).
// ---------------------------------------------------------------------------
__global__ __launch_bounds__(1024) void zero_counts_kernel()
{
    int i = blockIdx.x * 1024 + threadIdx.x;
    if (i < N_NODES) g_counts[i] = 0;
}

__global__ __launch_bounds__(1024) void hist_kernel(const int* __restrict__ dst)
{
    int i = blockIdx.x * 1024 + threadIdx.x;
    if (i < N_EDGES) atomicAdd(&g_counts[dst[i]], 1);
}

// Block-level exclusive scan (Hillis-Steele over 1024).
__global__ __launch_bounds__(1024) void scan1_kernel()
{
    __shared__ int s[1024];
    int i = blockIdx.x * 1024 + threadIdx.x;
    int v = (i < N_NODES) ? g_counts[i] : 0;
    s[threadIdx.x] = v;
    __syncthreads();
    #pragma unroll
    for (int d = 1; d < 1024; d <<= 1) {
        int t = (threadIdx.x >= d) ? s[threadIdx.x - d] : 0;
        __syncthreads();
        s[threadIdx.x] += t;
        __syncthreads();
    }
    if (i < N_NODES) g_offsets[i] = s[threadIdx.x] - v;   // exclusive
    if (threadIdx.x == 1023) g_blockSums[blockIdx.x] = s[1023];
}

__global__ __launch_bounds__(128) void scan2_kernel()
{
    __shared__ int s[128];
    int tid = threadIdx.x;
    int v = (tid < SCAN_BLOCKS) ? g_blockSums[tid] : 0;
    s[tid] = v;
    __syncthreads();
    #pragma unroll
    for (int d = 1; d < 128; d <<= 1) {
        int t = (tid >= d) ? s[tid - d] : 0;
        __syncthreads();
        s[tid] += t;
        __syncthreads();
    }
    if (tid < SCAN_BLOCKS) g_blockSumsScanned[tid] = s[tid] - v;
}

__global__ __launch_bounds__(1024) void scan3_kernel()
{
    int i = blockIdx.x * 1024 + threadIdx.x;
    if (i < N_NODES) {
        int off = g_offsets[i] + g_blockSumsScanned[blockIdx.x];
        g_offsets[i] = off;
        g_cursor[i]  = off;
    }
}

__global__ __launch_bounds__(1024) void scatter_kernel(
    const int* __restrict__ src,
    const int* __restrict__ dst,
    const float* __restrict__ e)
{
    int i = blockIdx.x * 1024 + threadIdx.x;
    if (i >= N_EDGES) return;
    int d = dst[i];
    int p = atomicAdd(&g_cursor[d], 1);
    g_sorted[p] = make_int2(src[i], __float_as_int(e[i]));
}

// ---------------------------------------------------------------------------
// Aggregate: 16 lanes per node, lane c owns float4 chunk c.
// Register accumulation, fused ReLU, single write. No atomics.
// ---------------------------------------------------------------------------
__global__ __launch_bounds__(256) void agg_kernel(float* __restrict__ out)
{
    int t = blockIdx.x * 256 + threadIdx.x;
    int node = t >> 4;
    int c    = t & 15;
    if (node >= N_NODES) return;

    int beg = g_offsets[node];
    int deg = g_counts[node];

    const float4* h4 = (const float4*)g_h;
    float4 acc = make_float4(0.f, 0.f, 0.f, 0.f);

    int j = 0;
    // 2-wide software pipeline to expose MLP on the L2-resident gather.
    for (; j + 2 <= deg; j += 2) {
        int2 r0 = g_sorted[beg + j];
        int2 r1 = g_sorted[beg + j + 1];
        float4 h0 = h4[(size_t)r0.x * 16 + c];
        float4 h1 = h4[(size_t)r1.x * 16 + c];
        float w0 = __int_as_float(r0.y);
        float w1 = __int_as_float(r1.y);
        acc.x += h0.x * w0; acc.y += h0.y * w0;
        acc.z += h0.z * w0; acc.w += h0.w * w0;
        acc.x += h1.x * w1; acc.y += h1.y * w1;
        acc.z += h1.z * w1; acc.w += h1.w * w1;
    }
    if (j < deg) {
        int2 r0 = g_sorted[beg + j];
        float4 h0 = h4[(size_t)r0.x * 16 + c];
        float w0 = __int_as_float(r0.y);
        acc.x += h0.x * w0; acc.y += h0.y * w0;
        acc.z += h0.z * w0; acc.w += h0.w * w0;
    }

    acc.x = fmaxf(acc.x, 0.f);
    acc.y = fmaxf(acc.y, 0.f);
    acc.z = fmaxf(acc.z, 0.f);
    acc.w = fmaxf(acc.w, 0.f);
    ((float4*)out)[(size_t)node * 16 + c] = acc;
}

extern "C" void kernel_launch(void* const* d_in, const int* in_sizes, int n_in,
                              void* d_out, int out_size)
{
    const float* feat = (const float*)d_in[0];
    const int*   src  = (const int*)d_in[1];
    const int*   dst  = (const int*)d_in[2];
    const float* e    = (const float*)d_in[3];
    const float* W_w  = (const float*)d_in[4];
    const float* W_b  = (const float*)d_in[5];
    float* out = (float*)d_out;

    const int edgeBlocks = (N_EDGES + 1023) / 1024;   // 1563
    const int nodeBlocks = (N_NODES + 1023) / 1024;   // 98

    // CSR build
    zero_counts_kernel<<<nodeBlocks, 1024>>>();
    hist_kernel<<<edgeBlocks, 1024>>>(dst);
    scan1_kernel<<<SCAN_BLOCKS, 1024>>>();
    scan2_kernel<<<1, 128>>>();
    scan3_kernel<<<SCAN_BLOCKS, 1024>>>();
    scatter_kernel<<<edgeBlocks, 1024>>>(src, dst, e);

    // Projection
    proj_kernel<<<(N_NODES + TM - 1) / TM, 256>>>(feat, W_w, W_b);

    // Aggregate + ReLU + write (covers every output element; no memset needed)
    agg_kernel<<<(N_NODES * 16 + 255) / 256, 256>>>(out);
}